// round 1
// baseline (speedup 1.0000x reference)
#include <cuda_runtime.h>
#include <math.h>

// Problem constants
#define TOKENS 2048      // B*S = 4*512
#define HDIM   2048
#define H2DIM  1024
#define NE     16        // experts
#define NMOD   4
#define CAP    768

// Output layout (floats): dispatch [T,E,CAP], combine [T,E,CAP], router_probs [T,E], aux [1]
static constexpr long long C_OFF   = (long long)TOKENS * NE * CAP;   // 25165824
static constexpr long long RP_OFF  = 2 * C_OFF;                      // 50331648
static constexpr long long AUX_OFF = RP_OFF + (long long)TOKENS * NE;// 50364416

// ---------------- scratch (device globals; no allocation allowed) -------------
__device__ float g_T1[TOKENS * HDIM];     // relu(hs@Wm1+bm1), later relu(hs@Wg1+bg1)
__device__ float g_T2[TOKENS * HDIM];     // missing_rep
__device__ float g_S1[TOKENS * H2DIM];    // per-modality hidden (reused sequentially)
__device__ float g_glog[TOKENS * NE];
__device__ float g_slog[NMOD * TOKENS * NE];
__device__ float g_partial[8 * NE];       // per-block expert prob sums (8 router blocks)

// ---------------- zero-fill the dispatch/combine regions ---------------------
__global__ void zero_kernel(float4* __restrict__ p, int n4) {
    int i = blockIdx.x * blockDim.x + threadIdx.x;
    int stride = gridDim.x * blockDim.x;
    float4 z = make_float4(0.f, 0.f, 0.f, 0.f);
    for (; i < n4; i += stride) p[i] = z;
}

// ---------------- big GEMM: C[M,N] = act(A[M,Kd] @ W[Kd,N] + bias[N]) --------
// 128x128 block tile, BK=16, 256 threads, 8x8 per-thread register tile.
// M implied by gridDim.y*128. All dims multiples of 128 / 16.
__global__ __launch_bounds__(256) void gemm_kernel(
    const float* __restrict__ A, const float* __restrict__ W,
    const float* __restrict__ bias, float* __restrict__ C,
    int N, int Kd, int do_relu)
{
    __shared__ float As[16][132];   // [k][m], padded
    __shared__ float Bs[16][128];   // [k][n]

    const int tid = threadIdx.x;
    const int tx = tid & 15;        // n-tile coord
    const int ty = tid >> 4;        // m-tile coord
    const int bm = blockIdx.y * 128;
    const int bn = blockIdx.x * 128;

    float acc[8][8];
#pragma unroll
    for (int i = 0; i < 8; i++)
#pragma unroll
        for (int j = 0; j < 8; j++) acc[i][j] = 0.f;

    const float* Ab = A + (size_t)bm * Kd;
    const float* Wb = W + bn;

    for (int k0 = 0; k0 < Kd; k0 += 16) {
        // Load A tile (128 rows x 16 k), transpose into As[k][m]
#pragma unroll
        for (int l = 0; l < 2; l++) {
            int id  = tid + l * 256;          // 0..511
            int row = id >> 2;                // 0..127
            int seg = (id & 3) << 2;          // 0,4,8,12
            float4 v = *(const float4*)(Ab + (size_t)row * Kd + k0 + seg);
            As[seg + 0][row] = v.x;
            As[seg + 1][row] = v.y;
            As[seg + 2][row] = v.z;
            As[seg + 3][row] = v.w;
        }
        // Load W tile (16 k x 128 n), direct
#pragma unroll
        for (int l = 0; l < 2; l++) {
            int id  = tid + l * 256;
            int kr  = id >> 5;                // 0..15
            int col = (id & 31) << 2;         // 0..124
            *(float4*)(&Bs[kr][col]) = *(const float4*)(Wb + (size_t)(k0 + kr) * N + col);
        }
        __syncthreads();

#pragma unroll
        for (int k = 0; k < 16; k++) {
            float a[8], b[8];
            *(float4*)(a)     = *(const float4*)(&As[k][ty * 8]);
            *(float4*)(a + 4) = *(const float4*)(&As[k][ty * 8 + 4]);
            *(float4*)(b)     = *(const float4*)(&Bs[k][tx * 8]);
            *(float4*)(b + 4) = *(const float4*)(&Bs[k][tx * 8 + 4]);
#pragma unroll
            for (int i = 0; i < 8; i++)
#pragma unroll
                for (int j = 0; j < 8; j++)
                    acc[i][j] = fmaf(a[i], b[j], acc[i][j]);
        }
        __syncthreads();
    }

    float bcol[8];
    *(float4*)(bcol)     = *(const float4*)(bias + bn + tx * 8);
    *(float4*)(bcol + 4) = *(const float4*)(bias + bn + tx * 8 + 4);
#pragma unroll
    for (int i = 0; i < 8; i++) {
        float o[8];
#pragma unroll
        for (int j = 0; j < 8; j++) {
            float v = acc[i][j] + bcol[j];
            o[j] = do_relu ? fmaxf(v, 0.f) : v;
        }
        float* Crow = C + (size_t)(bm + ty * 8 + i) * N + bn + tx * 8;
        *(float4*)(Crow)     = *(float4*)(o);
        *(float4*)(Crow + 4) = *(float4*)(o + 4);
    }
}

// ---------------- skinny GEMM: out[T,16] = X[T,Kd] @ W[Kd,16] + bias[16] -----
// 16 tokens x 16 experts per block (256 threads), staged in smem in 256-chunks.
__global__ __launch_bounds__(256) void logits_kernel(
    const float* __restrict__ X, const float* __restrict__ W,
    const float* __restrict__ bias, float* __restrict__ out, int Kd)
{
    __shared__ float xin[16][260];   // padded: adjacent tokens hit different banks
    __shared__ float wt[NE][257];    // transposed W chunk, pad 257 -> lanes e conflict-free

    const int tid = threadIdx.x;
    const int tokbase = blockIdx.x * 16;
    const int tok = tid >> 4;
    const int e   = tid & 15;

    float acc = 0.f;
    for (int c = 0; c < Kd; c += 256) {
#pragma unroll
        for (int l = 0; l < 4; l++) {
            int id  = tid + l * 256;          // 0..1023 float4s
            int t   = id >> 6;                // 0..15
            int seg = (id & 63) << 2;         // 0..252
            *(float4*)(&xin[t][seg]) =
                *(const float4*)(X + (size_t)(tokbase + t) * Kd + c + seg);
        }
#pragma unroll
        for (int l = 0; l < 4; l++) {
            int id = tid + l * 256;
            int r  = id >> 2;                 // 0..255
            int e4 = (id & 3) << 2;           // 0,4,8,12
            float4 v = *(const float4*)(W + (size_t)(c + r) * NE + e4);
            wt[e4 + 0][r] = v.x;
            wt[e4 + 1][r] = v.y;
            wt[e4 + 2][r] = v.z;
            wt[e4 + 3][r] = v.w;
        }
        __syncthreads();
#pragma unroll 8
        for (int h = 0; h < 256; h++)
            acc = fmaf(xin[tok][h], wt[e][h], acc);
        __syncthreads();
    }
    out[(size_t)(tokbase + tok) * NE + e] = acc + bias[e];
}

// ---------------- router: softmaxes, blend, top-4, scatter, partial sums -----
__global__ __launch_bounds__(256) void router_kernel(
    const float* __restrict__ glog, const float* __restrict__ slog,
    float* __restrict__ out, float* __restrict__ partial)
{
    __shared__ float sh[256][NE];
    const int tid = threadIdx.x;
    const int tok = blockIdx.x * 256 + tid;

    float probs[NE];
    // generalized router softmax, weighted 0.7
    {
        float g[NE];
#pragma unroll
        for (int i = 0; i < NE; i++) g[i] = glog[(size_t)tok * NE + i];
        float mx = g[0];
#pragma unroll
        for (int i = 1; i < NE; i++) mx = fmaxf(mx, g[i]);
        float s = 0.f;
#pragma unroll
        for (int i = 0; i < NE; i++) { g[i] = expf(g[i] - mx); s += g[i]; }
        float inv = 0.7f / s;
#pragma unroll
        for (int i = 0; i < NE; i++) probs[i] = g[i] * inv;
    }
    // specialized routers: 0.3 * (sum of 4 softmaxes) / 2 = 0.15 each
#pragma unroll
    for (int m = 0; m < NMOD; m++) {
        float g[NE];
#pragma unroll
        for (int i = 0; i < NE; i++)
            g[i] = slog[((size_t)m * TOKENS + tok) * NE + i];
        float mx = g[0];
#pragma unroll
        for (int i = 1; i < NE; i++) mx = fmaxf(mx, g[i]);
        float s = 0.f;
#pragma unroll
        for (int i = 0; i < NE; i++) { g[i] = expf(g[i] - mx); s += g[i]; }
        float inv = 0.15f / s;
#pragma unroll
        for (int i = 0; i < NE; i++) probs[i] += g[i] * inv;
    }

    // router_probs
#pragma unroll
    for (int i = 0; i < NE; i++)
        out[RP_OFF + (size_t)tok * NE + i] = probs[i];

    // top-4 (first occurrence on tie, matching lax.top_k lowest-index rule)
    unsigned used = 0;
    int   idx[4];
    float val[4];
    float vsum = 0.f;
#pragma unroll
    for (int k = 0; k < 4; k++) {
        float best = -1.f;  // probs > 0 always
        int bi = 0;
#pragma unroll
        for (int i = 0; i < NE; i++) {
            bool ok = !((used >> i) & 1u);
            if (ok && probs[i] > best) { best = probs[i]; bi = i; }
        }
        used |= (1u << bi);
        idx[k] = bi; val[k] = best; vsum += best;
    }
    float invv = 1.f / vsum;
#pragma unroll
    for (int k = 0; k < 4; k++) {
        size_t base = ((size_t)tok * NE + idx[k]) * CAP;
        out[base]         = 1.f;          // dispatch slot 0
        out[C_OFF + base] = val[k] * invv; // combine slot 0
    }

    // deterministic per-block expert prob sums (for aux loss)
#pragma unroll
    for (int i = 0; i < NE; i++) sh[tid][i] = probs[i];
    __syncthreads();
    if (tid < NE) {
        float s = 0.f;
        for (int i = 0; i < 256; i++) s += sh[i][tid];
        partial[blockIdx.x * NE + tid] = s;
    }
}

// ---------------- aux loss -----------------------------------------------
__global__ void aux_kernel(const float* __restrict__ partial, float* __restrict__ out)
{
    const int tid = threadIdx.x;
    float v = 0.f;
    if (tid < NE) {
        float s = 0.f;
#pragma unroll
        for (int b = 0; b < 8; b++) s += partial[b * NE + tid];
        float mp = s * (1.f / (float)TOKENS);
        v = mp * logf(mp * (float)NE + 1e-9f);
    }
#pragma unroll
    for (int off = 16; off > 0; off >>= 1)
        v += __shfl_down_sync(0xffffffffu, v, off);
    if (tid == 0) out[AUX_OFF] = v;
}

// ---------------- launch ---------------------------------------------------
extern "C" void kernel_launch(void* const* d_in, const int* in_sizes, int n_in,
                              void* d_out, int out_size)
{
    const float* hs   = (const float*)d_in[0];
    const float* mimg = (const float*)d_in[1];
    const float* mgen = (const float*)d_in[2];
    const float* Wg1  = (const float*)d_in[3];
    const float* bg1  = (const float*)d_in[4];
    const float* Wg2  = (const float*)d_in[5];
    const float* bg2  = (const float*)d_in[6];
    const float* Wm1  = (const float*)d_in[7];
    const float* bm1  = (const float*)d_in[8];
    const float* Wm2  = (const float*)d_in[9];
    const float* bm2  = (const float*)d_in[10];
    const float* Ws1  = (const float*)d_in[11];
    const float* bs1  = (const float*)d_in[12];
    const float* Ws2  = (const float*)d_in[13];
    const float* bs2  = (const float*)d_in[14];
    float* out = (float*)d_out;

    float *T1, *T2, *S1, *glog, *slog, *partial;
    cudaGetSymbolAddress((void**)&T1,      g_T1);
    cudaGetSymbolAddress((void**)&T2,      g_T2);
    cudaGetSymbolAddress((void**)&S1,      g_S1);
    cudaGetSymbolAddress((void**)&glog,    g_glog);
    cudaGetSymbolAddress((void**)&slog,    g_slog);
    cudaGetSymbolAddress((void**)&partial, g_partial);

    // 1. zero dispatch + combine regions (50,331,648 floats = 12,582,912 float4)
    zero_kernel<<<4096, 256>>>((float4*)out, (int)(2 * C_OFF / 4));

    dim3 gbig(16, 16);   // N=2048, M=2048
    dim3 gmid(8, 16);    // N=1024, M=2048

    // 2. missing-modality encoder
    gemm_kernel<<<gbig, 256>>>(hs, Wm1, bm1, T1, HDIM, HDIM, 1);
    gemm_kernel<<<gbig, 256>>>(T1, Wm2, bm2, T2, HDIM, HDIM, 0);

    // 3. generalized router
    gemm_kernel<<<gbig, 256>>>(hs, Wg1, bg1, T1, HDIM, HDIM, 1);
    logits_kernel<<<128, 256>>>(T1, Wg2, bg2, glog, HDIM);

    // 4. specialized routers (missing modalities use T2)
    for (int m = 0; m < NMOD; m++) {
        const float* data = (m == 0) ? mimg : (m == 1) ? mgen : T2;
        gemm_kernel<<<gmid, 256>>>(data, Ws1 + (size_t)m * HDIM * H2DIM,
                                   bs1 + (size_t)m * H2DIM, S1, H2DIM, HDIM, 1);
        logits_kernel<<<128, 256>>>(S1, Ws2 + (size_t)m * H2DIM * NE,
                                    bs2 + (size_t)m * NE,
                                    slog + (size_t)m * TOKENS * NE, H2DIM);
    }

    // 5. router epilogue + aux loss
    router_kernel<<<8, 256>>>(glog, slog, out, partial);
    aux_kernel<<<1, 32>>>(partial, out);
}

// round 3
// speedup vs baseline: 1.2986x; 1.2986x over previous
#include <cuda_runtime.h>
#include <math.h>
#include <stdint.h>

#define TOKENS 2048
#define HDIM   2048
#define H2DIM  1024
#define NE     16
#define NMOD   4
#define CAP    768
#define KD     2048   // all GEMMs have K = 2048

static constexpr long long C_OFF   = (long long)TOKENS * NE * CAP;
static constexpr long long RP_OFF  = 2 * C_OFF;
static constexpr long long AUX_OFF = RP_OFF + (long long)TOKENS * NE;

__device__ float g_T1[TOKENS * HDIM];
__device__ float g_T2[TOKENS * HDIM];
__device__ float g_S1[TOKENS * H2DIM];
__device__ float g_glog[TOKENS * NE];
__device__ float g_slog[NMOD * TOKENS * NE];
__device__ float g_partial[8 * NE];

// ---------------- helpers ---------------------------------------------------
__device__ __forceinline__ void split2(float v, uint32_t& hb, uint32_t& lb) {
    asm("cvt.rna.tf32.f32 %0, %1;" : "=r"(hb) : "f"(v));
    float lo = v - __uint_as_float(hb);
    asm("cvt.rna.tf32.f32 %0, %1;" : "=r"(lb) : "f"(lo));
}

__device__ __forceinline__ void mma_tf32(float* c, const uint32_t* a, const uint32_t* b) {
    asm volatile(
        "mma.sync.aligned.m16n8k8.row.col.f32.tf32.tf32.f32 "
        "{%0,%1,%2,%3}, {%4,%5,%6,%7}, {%8,%9}, {%0,%1,%2,%3};"
        : "+f"(c[0]), "+f"(c[1]), "+f"(c[2]), "+f"(c[3])
        : "r"(a[0]), "r"(a[1]), "r"(a[2]), "r"(a[3]), "r"(b[0]), "r"(b[1]));
}

// ---------------- zero-fill --------------------------------------------------
__global__ void zero_kernel(float4* __restrict__ p, int n4) {
    int i = blockIdx.x * blockDim.x + threadIdx.x;
    int stride = gridDim.x * blockDim.x;
    float4 z = make_float4(0.f, 0.f, 0.f, 0.f);
    for (; i < n4; i += stride) p[i] = z;
}

// ---------------- HMMA 3xTF32 GEMM: C = act(A[M,2048] @ W[2048,N] + bias) ----
// 128x128 CTA tile, BK=32, 256 threads (8 warps, 64x32 warp tiles).
// Smem (uint32 words):
//   Ah [128][40]  (m-major, padded: bank = 8*gid + tig pattern, conflict-free)
//   Al [128][40]
//   Bh [32][136]  (k-major [k][n], pad 136 -> bank = 8*tig + gid, conflict-free)
//   Bl [32][136]
#define AH_OFF 0
#define AL_OFF (128 * 40)
#define BH_OFF (2 * 128 * 40)
#define BL_OFF (BH_OFF + 32 * 136)
#define SMEM_WORDS (BL_OFF + 32 * 136)
#define SMEM_BYTES (SMEM_WORDS * 4)

__global__ __launch_bounds__(256) void gemm_hmma(
    const float* __restrict__ A, const float* __restrict__ W,
    const float* __restrict__ bias, float* __restrict__ C,
    int N, int do_relu)
{
    extern __shared__ uint32_t sm[];
    uint32_t* Ah = sm + AH_OFF;
    uint32_t* Al = sm + AL_OFF;
    uint32_t* Bh = sm + BH_OFF;
    uint32_t* Bl = sm + BL_OFF;

    const int tid  = threadIdx.x;
    const int wid  = tid >> 5;
    const int lane = tid & 31;
    const int gid  = lane >> 2;
    const int tig  = lane & 3;
    const int wm   = (wid & 1) * 64;
    const int wn   = (wid >> 1) * 32;
    const int bm   = blockIdx.y * 128;
    const int bn   = blockIdx.x * 128;

    // global load mapping
    const int arow0 = tid >> 3;          // + 32*l
    const int aseg  = (tid & 7) * 4;     // k offset within BK
    const int bkr0  = tid >> 5;          // + 8*l
    const int bcol  = (tid & 31) * 4;    // n offset within 128

    float acc[4][4][4];
#pragma unroll
    for (int mt = 0; mt < 4; mt++)
#pragma unroll
        for (int nt = 0; nt < 4; nt++)
#pragma unroll
            for (int r = 0; r < 4; r++) acc[mt][nt][r] = 0.f;

    float4 av[4], bv[4];
    // preload kb = 0
#pragma unroll
    for (int l = 0; l < 4; l++)
        av[l] = *(const float4*)(A + (size_t)(bm + arow0 + 32 * l) * KD + aseg);
#pragma unroll
    for (int l = 0; l < 4; l++)
        bv[l] = *(const float4*)(W + (size_t)(bkr0 + 8 * l) * N + bn + bcol);

    for (int kb = 0; kb < KD / 32; kb++) {
        // ---- split + store to smem ----
#pragma unroll
        for (int l = 0; l < 4; l++) {
            uint4 h, lo;
            split2(av[l].x, h.x, lo.x); split2(av[l].y, h.y, lo.y);
            split2(av[l].z, h.z, lo.z); split2(av[l].w, h.w, lo.w);
            int off = (arow0 + 32 * l) * 40 + aseg;
            *(uint4*)(Ah + off) = h;
            *(uint4*)(Al + off) = lo;
        }
#pragma unroll
        for (int l = 0; l < 4; l++) {
            uint4 h, lo;
            split2(bv[l].x, h.x, lo.x); split2(bv[l].y, h.y, lo.y);
            split2(bv[l].z, h.z, lo.z); split2(bv[l].w, h.w, lo.w);
            int off = (bkr0 + 8 * l) * 136 + bcol;
            *(uint4*)(Bh + off) = h;
            *(uint4*)(Bl + off) = lo;
        }
        __syncthreads();

        // ---- prefetch next tile (hidden behind MMAs) ----
        if (kb + 1 < KD / 32) {
            const float* Ap = A + (size_t)bm * KD + (kb + 1) * 32;
            const float* Wp = W + (size_t)(kb + 1) * 32 * N + bn;
#pragma unroll
            for (int l = 0; l < 4; l++)
                av[l] = *(const float4*)(Ap + (size_t)(arow0 + 32 * l) * KD + aseg);
#pragma unroll
            for (int l = 0; l < 4; l++)
                bv[l] = *(const float4*)(Wp + (size_t)(bkr0 + 8 * l) * N + bcol);
        }

        // ---- MMA phase: 4 k8-steps, 3-pass tf32 split ----
#pragma unroll
        for (int k0 = 0; k0 < 32; k0 += 8) {
            uint32_t fa[4][4], fa2[4][4], fb[4][2];
            // Ah frags
#pragma unroll
            for (int mt = 0; mt < 4; mt++) {
                int rbase = (wm + mt * 16 + gid) * 40 + k0 + tig;
                fa[mt][0] = Ah[rbase];
                fa[mt][1] = Ah[rbase + 8 * 40];
                fa[mt][2] = Ah[rbase + 4];
                fa[mt][3] = Ah[rbase + 8 * 40 + 4];
            }
            // Bh frags
#pragma unroll
            for (int nt = 0; nt < 4; nt++) {
                int cbase = (k0 + tig) * 136 + wn + nt * 8 + gid;
                fb[nt][0] = Bh[cbase];
                fb[nt][1] = Bh[cbase + 4 * 136];
            }
            // pass 1: Ah * Bh
#pragma unroll
            for (int mt = 0; mt < 4; mt++)
#pragma unroll
                for (int nt = 0; nt < 4; nt++)
                    mma_tf32(acc[mt][nt], fa[mt], fb[nt]);
            // Al frags; pass 2: Al * Bh
#pragma unroll
            for (int mt = 0; mt < 4; mt++) {
                int rbase = (wm + mt * 16 + gid) * 40 + k0 + tig;
                fa2[mt][0] = Al[rbase];
                fa2[mt][1] = Al[rbase + 8 * 40];
                fa2[mt][2] = Al[rbase + 4];
                fa2[mt][3] = Al[rbase + 8 * 40 + 4];
            }
#pragma unroll
            for (int mt = 0; mt < 4; mt++)
#pragma unroll
                for (int nt = 0; nt < 4; nt++)
                    mma_tf32(acc[mt][nt], fa2[mt], fb[nt]);
            // Bl frags (reuse fb); pass 3: Ah * Bl
#pragma unroll
            for (int nt = 0; nt < 4; nt++) {
                int cbase = (k0 + tig) * 136 + wn + nt * 8 + gid;
                fb[nt][0] = Bl[cbase];
                fb[nt][1] = Bl[cbase + 4 * 136];
            }
#pragma unroll
            for (int mt = 0; mt < 4; mt++)
#pragma unroll
                for (int nt = 0; nt < 4; nt++)
                    mma_tf32(acc[mt][nt], fa[mt], fb[nt]);
        }
        __syncthreads();
    }

    // ---- epilogue ----
#pragma unroll
    for (int nt = 0; nt < 4; nt++) {
        int col = bn + wn + nt * 8 + 2 * tig;
        float b0 = bias[col], b1 = bias[col + 1];
#pragma unroll
        for (int mt = 0; mt < 4; mt++) {
            int row = bm + wm + mt * 16 + gid;
            float v0 = acc[mt][nt][0] + b0;
            float v1 = acc[mt][nt][1] + b1;
            float v2 = acc[mt][nt][2] + b0;
            float v3 = acc[mt][nt][3] + b1;
            if (do_relu) {
                v0 = fmaxf(v0, 0.f); v1 = fmaxf(v1, 0.f);
                v2 = fmaxf(v2, 0.f); v3 = fmaxf(v3, 0.f);
            }
            *(float2*)(C + (size_t)row * N + col)       = make_float2(v0, v1);
            *(float2*)(C + (size_t)(row + 8) * N + col) = make_float2(v2, v3);
        }
    }
}

// ---------------- logits v2: warp-per-token, out[T,16] = X @ W + bias --------
__global__ __launch_bounds__(128) void logits_kernel(
    const float* __restrict__ X, const float* __restrict__ W,
    const float* __restrict__ bias, float* __restrict__ out, int Kd)
{
    __shared__ float wt[NE][257];
    const int tid = threadIdx.x;
    const int wid = tid >> 5;
    const int lane = tid & 31;
    const int tok = blockIdx.x * 4 + wid;

    float acc[NE];
#pragma unroll
    for (int e = 0; e < NE; e++) acc[e] = 0.f;

    const float* xrow = X + (size_t)tok * Kd;

    for (int c = 0; c < Kd; c += 256) {
        // load + transpose W chunk [256][16] -> wt[e][k]
#pragma unroll
        for (int l = 0; l < 8; l++) {
            int id = tid + l * 128;        // 0..1023 float4
            int k  = id >> 2;              // 0..255
            int e4 = (id & 3) << 2;
            float4 v = *(const float4*)(W + (size_t)(c + k) * NE + e4);
            wt[e4 + 0][k] = v.x;
            wt[e4 + 1][k] = v.y;
            wt[e4 + 2][k] = v.z;
            wt[e4 + 3][k] = v.w;
        }
        __syncthreads();
#pragma unroll
        for (int i = 0; i < 8; i++) {
            int kk = i * 32 + lane;
            float xv = xrow[c + kk];
#pragma unroll
            for (int e = 0; e < NE; e++)
                acc[e] = fmaf(xv, wt[e][kk], acc[e]);
        }
        __syncthreads();
    }
    // warp reduction
#pragma unroll
    for (int off = 16; off > 0; off >>= 1)
#pragma unroll
        for (int e = 0; e < NE; e++)
            acc[e] += __shfl_xor_sync(0xffffffffu, acc[e], off);
    if (lane == 0) {
#pragma unroll
        for (int e = 0; e < NE; e++)
            out[(size_t)tok * NE + e] = acc[e] + bias[e];
    }
}

// ---------------- router ------------------------------------------------------
__global__ __launch_bounds__(256) void router_kernel(
    const float* __restrict__ glog, const float* __restrict__ slog,
    float* __restrict__ out, float* __restrict__ partial)
{
    __shared__ float sh[256][NE];
    const int tid = threadIdx.x;
    const int tok = blockIdx.x * 256 + tid;

    float probs[NE];
    {
        float g[NE];
#pragma unroll
        for (int i = 0; i < NE; i++) g[i] = glog[(size_t)tok * NE + i];
        float mx = g[0];
#pragma unroll
        for (int i = 1; i < NE; i++) mx = fmaxf(mx, g[i]);
        float s = 0.f;
#pragma unroll
        for (int i = 0; i < NE; i++) { g[i] = expf(g[i] - mx); s += g[i]; }
        float inv = 0.7f / s;
#pragma unroll
        for (int i = 0; i < NE; i++) probs[i] = g[i] * inv;
    }
#pragma unroll
    for (int m = 0; m < NMOD; m++) {
        float g[NE];
#pragma unroll
        for (int i = 0; i < NE; i++)
            g[i] = slog[((size_t)m * TOKENS + tok) * NE + i];
        float mx = g[0];
#pragma unroll
        for (int i = 1; i < NE; i++) mx = fmaxf(mx, g[i]);
        float s = 0.f;
#pragma unroll
        for (int i = 0; i < NE; i++) { g[i] = expf(g[i] - mx); s += g[i]; }
        float inv = 0.15f / s;
#pragma unroll
        for (int i = 0; i < NE; i++) probs[i] += g[i] * inv;
    }

#pragma unroll
    for (int i = 0; i < NE; i++)
        out[RP_OFF + (size_t)tok * NE + i] = probs[i];

    unsigned used = 0;
    int idx[4]; float val[4]; float vsum = 0.f;
#pragma unroll
    for (int k = 0; k < 4; k++) {
        float best = -1.f; int bi = 0;
#pragma unroll
        for (int i = 0; i < NE; i++) {
            bool ok = !((used >> i) & 1u);
            if (ok && probs[i] > best) { best = probs[i]; bi = i; }
        }
        used |= (1u << bi);
        idx[k] = bi; val[k] = best; vsum += best;
    }
    float invv = 1.f / vsum;
#pragma unroll
    for (int k = 0; k < 4; k++) {
        size_t base = ((size_t)tok * NE + idx[k]) * CAP;
        out[base]         = 1.f;
        out[C_OFF + base] = val[k] * invv;
    }

#pragma unroll
    for (int i = 0; i < NE; i++) sh[tid][i] = probs[i];
    __syncthreads();
    if (tid < NE) {
        float s = 0.f;
        for (int i = 0; i < 256; i++) s += sh[i][tid];
        partial[blockIdx.x * NE + tid] = s;
    }
}

// ---------------- aux loss ----------------------------------------------------
__global__ void aux_kernel(const float* __restrict__ partial, float* __restrict__ out)
{
    const int tid = threadIdx.x;
    float v = 0.f;
    if (tid < NE) {
        float s = 0.f;
#pragma unroll
        for (int b = 0; b < 8; b++) s += partial[b * NE + tid];
        float mp = s * (1.f / (float)TOKENS);
        v = mp * logf(mp * (float)NE + 1e-9f);
    }
#pragma unroll
    for (int off = 16; off > 0; off >>= 1)
        v += __shfl_down_sync(0xffffffffu, v, off);
    if (tid == 0) out[AUX_OFF] = v;
}

// ---------------- launch ------------------------------------------------------
extern "C" void kernel_launch(void* const* d_in, const int* in_sizes, int n_in,
                              void* d_out, int out_size)
{
    const float* hs   = (const float*)d_in[0];
    const float* mimg = (const float*)d_in[1];
    const float* mgen = (const float*)d_in[2];
    const float* Wg1  = (const float*)d_in[3];
    const float* bg1  = (const float*)d_in[4];
    const float* Wg2  = (const float*)d_in[5];
    const float* bg2  = (const float*)d_in[6];
    const float* Wm1  = (const float*)d_in[7];
    const float* bm1  = (const float*)d_in[8];
    const float* Wm2  = (const float*)d_in[9];
    const float* bm2  = (const float*)d_in[10];
    const float* Ws1  = (const float*)d_in[11];
    const float* bs1  = (const float*)d_in[12];
    const float* Ws2  = (const float*)d_in[13];
    const float* bs2  = (const float*)d_in[14];
    float* out = (float*)d_out;

    float *T1, *T2, *S1, *glog, *slog, *partial;
    cudaGetSymbolAddress((void**)&T1,      g_T1);
    cudaGetSymbolAddress((void**)&T2,      g_T2);
    cudaGetSymbolAddress((void**)&S1,      g_S1);
    cudaGetSymbolAddress((void**)&glog,    g_glog);
    cudaGetSymbolAddress((void**)&slog,    g_slog);
    cudaGetSymbolAddress((void**)&partial, g_partial);

    cudaFuncSetAttribute(gemm_hmma,
                         cudaFuncAttributeMaxDynamicSharedMemorySize, SMEM_BYTES);

    zero_kernel<<<4096, 256>>>((float4*)out, (int)(2 * C_OFF / 4));

    dim3 gbig(16, 16);   // N=2048
    dim3 gmid(8, 16);    // N=1024

    // missing-modality encoder
    gemm_hmma<<<gbig, 256, SMEM_BYTES>>>(hs, Wm1, bm1, T1, HDIM, 1);
    gemm_hmma<<<gbig, 256, SMEM_BYTES>>>(T1, Wm2, bm2, T2, HDIM, 0);

    // generalized router
    gemm_hmma<<<gbig, 256, SMEM_BYTES>>>(hs, Wg1, bg1, T1, HDIM, 1);
    logits_kernel<<<512, 128>>>(T1, Wg2, bg2, glog, HDIM);

    // specialized routers
    for (int m = 0; m < NMOD; m++) {
        const float* data = (m == 0) ? mimg : (m == 1) ? mgen : T2;
        gemm_hmma<<<gmid, 256, SMEM_BYTES>>>(data, Ws1 + (size_t)m * HDIM * H2DIM,
                                             bs1 + (size_t)m * H2DIM, S1, H2DIM, 1);
        logits_kernel<<<512, 128>>>(S1, Ws2 + (size_t)m * H2DIM * NE,
                                    bs2 + (size_t)m * NE,
                                    slog + (size_t)m * TOKENS * NE, H2DIM);
    }

    router_kernel<<<8, 256>>>(glog, slog, out, partial);
    aux_kernel<<<1, 32>>>(partial, out);
}

// round 4
// speedup vs baseline: 1.3615x; 1.0485x over previous
#include <cuda_runtime.h>
#include <math.h>
#include <stdint.h>

#define TOKENS 2048
#define HDIM   2048
#define H2DIM  1024
#define NE     16
#define NMOD   4
#define CAP    768
#define KD     2048

static constexpr long long C_OFF   = (long long)TOKENS * NE * CAP;
static constexpr long long RP_OFF  = 2 * C_OFF;
static constexpr long long AUX_OFF = RP_OFF + (long long)TOKENS * NE;

// ---------------- device scratch --------------------------------------------
__device__ float g_T1[TOKENS * HDIM];
__device__ float g_T2[TOKENS * HDIM];
__device__ float g_S1[TOKENS * H2DIM];
__device__ float g_glog[TOKENS * NE];
__device__ float g_slog[NMOD * TOKENS * NE];
__device__ float g_partial[8 * NE];
// tf32 split planes
__device__ float g_HSh[TOKENS * HDIM];
__device__ float g_HSl[TOKENS * HDIM];
__device__ float g_ACTh[TOKENS * HDIM];
__device__ float g_ACTl[TOKENS * HDIM];
__device__ float g_Wh[HDIM * HDIM];
__device__ float g_Wl[HDIM * HDIM];

// ---------------- helpers ---------------------------------------------------
__device__ __forceinline__ void split2(float v, uint32_t& hb, uint32_t& lb) {
    asm("cvt.rna.tf32.f32 %0, %1;" : "=r"(hb) : "f"(v));
    float lo = v - __uint_as_float(hb);
    asm("cvt.rna.tf32.f32 %0, %1;" : "=r"(lb) : "f"(lo));
}

__device__ __forceinline__ void mma_tf32(float* c, const uint32_t* a, const uint32_t* b) {
    asm volatile(
        "mma.sync.aligned.m16n8k8.row.col.f32.tf32.tf32.f32 "
        "{%0,%1,%2,%3}, {%4,%5,%6,%7}, {%8,%9}, {%0,%1,%2,%3};"
        : "+f"(c[0]), "+f"(c[1]), "+f"(c[2]), "+f"(c[3])
        : "r"(a[0]), "r"(a[1]), "r"(a[2]), "r"(a[3]), "r"(b[0]), "r"(b[1]));
}

#define CP_ASYNC16(dst, src) \
    asm volatile("cp.async.cg.shared.global [%0], [%1], 16;" :: "r"(dst), "l"(src))
#define CP_COMMIT() asm volatile("cp.async.commit_group;" ::: "memory")
#define CP_WAIT2()  asm volatile("cp.async.wait_group 2;" ::: "memory")

// ---------------- zero-fill --------------------------------------------------
__global__ void zero_kernel(float4* __restrict__ p, int n4) {
    int i = blockIdx.x * blockDim.x + threadIdx.x;
    int stride = gridDim.x * blockDim.x;
    float4 z = make_float4(0.f, 0.f, 0.f, 0.f);
    for (; i < n4; i += stride) p[i] = z;
}

// ---------------- split: fp32 -> tf32 hi/lo planes ---------------------------
__global__ void split_kernel(const float4* __restrict__ src,
                             float4* __restrict__ hi, float4* __restrict__ lo, int n4) {
    int i = blockIdx.x * blockDim.x + threadIdx.x;
    int stride = gridDim.x * blockDim.x;
    for (; i < n4; i += stride) {
        float4 v = src[i];
        uint4 h, l;
        split2(v.x, h.x, l.x); split2(v.y, h.y, l.y);
        split2(v.z, h.z, l.z); split2(v.w, h.w, l.w);
        hi[i] = *(float4*)&h;
        lo[i] = *(float4*)&l;
    }
}

// ---------------- HMMA 3xTF32 GEMM with cp.async 4-stage pipeline ------------
// C[M,N] = act(A[M,2048] @ W[2048,N] + bias). 128x128 CTA tile, BK=16,
// 256 threads, 8 warps with 64x32 warp tiles. Operands pre-split to tf32 hi/lo.
// Stage layout (uint32 words): AH[128][20]=2560, AL=2560, BH[16][136]=2176, BL=2176.
#define AL_W   2560
#define BH_W   5120
#define BL_W   7296
#define STG_W  9472
#define STG_B  (STG_W * 4)
#define NSTG   4
#define SMEM_BYTES (NSTG * STG_B)   // 151552

__global__ __launch_bounds__(256) void gemm_split(
    const float* __restrict__ Ahg, const float* __restrict__ Alg,
    const float* __restrict__ Bhg, const float* __restrict__ Blg,
    const float* __restrict__ bias, float* __restrict__ C,
    int N, int do_relu)
{
    extern __shared__ uint32_t sm[];
    const int tid  = threadIdx.x;
    const int wid  = tid >> 5;
    const int lane = tid & 31;
    const int gid  = lane >> 2;
    const int tig  = lane & 3;
    const int wm   = (wid & 1) * 64;
    const int wn   = (wid >> 1) * 32;
    const int bm   = blockIdx.y * 128;
    const int bn   = blockIdx.x * 128;

    // cp.async per-thread mapping
    const int arow = tid >> 2;           // 0..63 ; second copy +64
    const int aseg = (tid & 3) * 4;      // 0,4,8,12
    const int bkr  = tid >> 5;           // 0..7 ; second copy +8
    const int bcol = (tid & 31) * 4;     // 0..124

    const float* aH0 = Ahg + (size_t)(bm + arow) * KD + aseg;
    const float* aH1 = aH0 + (size_t)64 * KD;
    const float* aL0 = Alg + (size_t)(bm + arow) * KD + aseg;
    const float* aL1 = aL0 + (size_t)64 * KD;
    const float* bH0 = Bhg + (size_t)bkr * N + bn + bcol;
    const float* bH1 = bH0 + (size_t)8 * N;
    const float* bL0 = Blg + (size_t)bkr * N + bn + bcol;
    const float* bL1 = bL0 + (size_t)8 * N;

    const uint32_t smbase = (uint32_t)__cvta_generic_to_shared(sm);
    const uint32_t dA0 = (uint32_t)(arow * 20 + aseg) * 4;
    const uint32_t dA1 = (uint32_t)((arow + 64) * 20 + aseg) * 4;
    const uint32_t dB0 = (uint32_t)(BH_W + bkr * 136 + bcol) * 4;
    const uint32_t dB1 = (uint32_t)(BH_W + (bkr + 8) * 136 + bcol) * 4;

    float acc[4][4][4];
#pragma unroll
    for (int mt = 0; mt < 4; mt++)
#pragma unroll
        for (int nt = 0; nt < 4; nt++)
#pragma unroll
            for (int r = 0; r < 4; r++) acc[mt][nt][r] = 0.f;

    const int KT = KD / 16;   // 128

#define ISSUE_STAGE(s, kb) do {                                   \
    uint32_t sb = smbase + (uint32_t)(s) * STG_B;                 \
    size_t ka = (size_t)(kb) * 16;                                \
    size_t kw = (size_t)(kb) * 16 * N;                            \
    CP_ASYNC16(sb + dA0,            aH0 + ka);                    \
    CP_ASYNC16(sb + dA1,            aH1 + ka);                    \
    CP_ASYNC16(sb + dA0 + AL_W * 4, aL0 + ka);                    \
    CP_ASYNC16(sb + dA1 + AL_W * 4, aL1 + ka);                    \
    CP_ASYNC16(sb + dB0,            bH0 + kw);                    \
    CP_ASYNC16(sb + dB1,            bH1 + kw);                    \
    CP_ASYNC16(sb + dB0 + 2176 * 4, bL0 + kw);                    \
    CP_ASYNC16(sb + dB1 + 2176 * 4, bL1 + kw);                    \
} while (0)

    // prologue: stages 0..2
    ISSUE_STAGE(0, 0); CP_COMMIT();
    ISSUE_STAGE(1, 1); CP_COMMIT();
    ISSUE_STAGE(2, 2); CP_COMMIT();

    for (int kb = 0; kb < KT; kb++) {
        CP_WAIT2();
        __syncthreads();

        const uint32_t* st = sm + (kb & 3) * STG_W;
        const uint32_t* AH = st;
        const uint32_t* ALo = st + AL_W;
        const uint32_t* BH = st + BH_W;
        const uint32_t* BLo = st + BL_W;

#pragma unroll
        for (int k0 = 0; k0 < 16; k0 += 8) {
            uint32_t fa[4][4], fa2[4][4], fb[4][2];
#pragma unroll
            for (int mt = 0; mt < 4; mt++) {
                int rbase = (wm + mt * 16 + gid) * 20 + k0 + tig;
                fa[mt][0] = AH[rbase];
                fa[mt][1] = AH[rbase + 8 * 20];
                fa[mt][2] = AH[rbase + 4];
                fa[mt][3] = AH[rbase + 8 * 20 + 4];
            }
#pragma unroll
            for (int nt = 0; nt < 4; nt++) {
                int cbase = (k0 + tig) * 136 + wn + nt * 8 + gid;
                fb[nt][0] = BH[cbase];
                fb[nt][1] = BH[cbase + 4 * 136];
            }
#pragma unroll
            for (int mt = 0; mt < 4; mt++)
#pragma unroll
                for (int nt = 0; nt < 4; nt++)
                    mma_tf32(acc[mt][nt], fa[mt], fb[nt]);
#pragma unroll
            for (int mt = 0; mt < 4; mt++) {
                int rbase = (wm + mt * 16 + gid) * 20 + k0 + tig;
                fa2[mt][0] = ALo[rbase];
                fa2[mt][1] = ALo[rbase + 8 * 20];
                fa2[mt][2] = ALo[rbase + 4];
                fa2[mt][3] = ALo[rbase + 8 * 20 + 4];
            }
#pragma unroll
            for (int mt = 0; mt < 4; mt++)
#pragma unroll
                for (int nt = 0; nt < 4; nt++)
                    mma_tf32(acc[mt][nt], fa2[mt], fb[nt]);
#pragma unroll
            for (int nt = 0; nt < 4; nt++) {
                int cbase = (k0 + tig) * 136 + wn + nt * 8 + gid;
                fb[nt][0] = BLo[cbase];
                fb[nt][1] = BLo[cbase + 4 * 136];
            }
#pragma unroll
            for (int mt = 0; mt < 4; mt++)
#pragma unroll
                for (int nt = 0; nt < 4; nt++)
                    mma_tf32(acc[mt][nt], fa[mt], fb[nt]);
        }

        if (kb + 3 < KT) ISSUE_STAGE((kb + 3) & 3, kb + 3);
        CP_COMMIT();
    }

    // ---- epilogue ----
#pragma unroll
    for (int nt = 0; nt < 4; nt++) {
        int col = bn + wn + nt * 8 + 2 * tig;
        float b0 = bias[col], b1 = bias[col + 1];
#pragma unroll
        for (int mt = 0; mt < 4; mt++) {
            int row = bm + wm + mt * 16 + gid;
            float v0 = acc[mt][nt][0] + b0;
            float v1 = acc[mt][nt][1] + b1;
            float v2 = acc[mt][nt][2] + b0;
            float v3 = acc[mt][nt][3] + b1;
            if (do_relu) {
                v0 = fmaxf(v0, 0.f); v1 = fmaxf(v1, 0.f);
                v2 = fmaxf(v2, 0.f); v3 = fmaxf(v3, 0.f);
            }
            *(float2*)(C + (size_t)row * N + col)       = make_float2(v0, v1);
            *(float2*)(C + (size_t)(row + 8) * N + col) = make_float2(v2, v3);
        }
    }
}

// ---------------- logits: warp-per-token, out[T,16] = X @ W + bias -----------
__global__ __launch_bounds__(128) void logits_kernel(
    const float* __restrict__ X, const float* __restrict__ W,
    const float* __restrict__ bias, float* __restrict__ out, int Kd)
{
    __shared__ float wt[NE][257];
    const int tid = threadIdx.x;
    const int wid = tid >> 5;
    const int lane = tid & 31;
    const int tok = blockIdx.x * 4 + wid;

    float acc[NE];
#pragma unroll
    for (int e = 0; e < NE; e++) acc[e] = 0.f;

    const float* xrow = X + (size_t)tok * Kd;

    for (int c = 0; c < Kd; c += 256) {
#pragma unroll
        for (int l = 0; l < 8; l++) {
            int id = tid + l * 128;
            int k  = id >> 2;
            int e4 = (id & 3) << 2;
            float4 v = *(const float4*)(W + (size_t)(c + k) * NE + e4);
            wt[e4 + 0][k] = v.x;
            wt[e4 + 1][k] = v.y;
            wt[e4 + 2][k] = v.z;
            wt[e4 + 3][k] = v.w;
        }
        __syncthreads();
#pragma unroll
        for (int i = 0; i < 8; i++) {
            int kk = i * 32 + lane;
            float xv = xrow[c + kk];
#pragma unroll
            for (int e = 0; e < NE; e++)
                acc[e] = fmaf(xv, wt[e][kk], acc[e]);
        }
        __syncthreads();
    }
#pragma unroll
    for (int off = 16; off > 0; off >>= 1)
#pragma unroll
        for (int e = 0; e < NE; e++)
            acc[e] += __shfl_xor_sync(0xffffffffu, acc[e], off);
    if (lane == 0) {
#pragma unroll
        for (int e = 0; e < NE; e++)
            out[(size_t)tok * NE + e] = acc[e] + bias[e];
    }
}

// ---------------- router ------------------------------------------------------
__global__ __launch_bounds__(256) void router_kernel(
    const float* __restrict__ glog, const float* __restrict__ slog,
    float* __restrict__ out, float* __restrict__ partial)
{
    __shared__ float sh[256][NE];
    const int tid = threadIdx.x;
    const int tok = blockIdx.x * 256 + tid;

    float probs[NE];
    {
        float g[NE];
#pragma unroll
        for (int i = 0; i < NE; i++) g[i] = glog[(size_t)tok * NE + i];
        float mx = g[0];
#pragma unroll
        for (int i = 1; i < NE; i++) mx = fmaxf(mx, g[i]);
        float s = 0.f;
#pragma unroll
        for (int i = 0; i < NE; i++) { g[i] = expf(g[i] - mx); s += g[i]; }
        float inv = 0.7f / s;
#pragma unroll
        for (int i = 0; i < NE; i++) probs[i] = g[i] * inv;
    }
#pragma unroll
    for (int m = 0; m < NMOD; m++) {
        float g[NE];
#pragma unroll
        for (int i = 0; i < NE; i++)
            g[i] = slog[((size_t)m * TOKENS + tok) * NE + i];
        float mx = g[0];
#pragma unroll
        for (int i = 1; i < NE; i++) mx = fmaxf(mx, g[i]);
        float s = 0.f;
#pragma unroll
        for (int i = 0; i < NE; i++) { g[i] = expf(g[i] - mx); s += g[i]; }
        float inv = 0.15f / s;
#pragma unroll
        for (int i = 0; i < NE; i++) probs[i] += g[i] * inv;
    }

#pragma unroll
    for (int i = 0; i < NE; i++)
        out[RP_OFF + (size_t)tok * NE + i] = probs[i];

    unsigned used = 0;
    int idx[4]; float val[4]; float vsum = 0.f;
#pragma unroll
    for (int k = 0; k < 4; k++) {
        float best = -1.f; int bi = 0;
#pragma unroll
        for (int i = 0; i < NE; i++) {
            bool ok = !((used >> i) & 1u);
            if (ok && probs[i] > best) { best = probs[i]; bi = i; }
        }
        used |= (1u << bi);
        idx[k] = bi; val[k] = best; vsum += best;
    }
    float invv = 1.f / vsum;
#pragma unroll
    for (int k = 0; k < 4; k++) {
        size_t base = ((size_t)tok * NE + idx[k]) * CAP;
        out[base]         = 1.f;
        out[C_OFF + base] = val[k] * invv;
    }

#pragma unroll
    for (int i = 0; i < NE; i++) sh[tid][i] = probs[i];
    __syncthreads();
    if (tid < NE) {
        float s = 0.f;
        for (int i = 0; i < 256; i++) s += sh[i][tid];
        partial[blockIdx.x * NE + tid] = s;
    }
}

// ---------------- aux loss ----------------------------------------------------
__global__ void aux_kernel(const float* __restrict__ partial, float* __restrict__ out)
{
    const int tid = threadIdx.x;
    float v = 0.f;
    if (tid < NE) {
        float s = 0.f;
#pragma unroll
        for (int b = 0; b < 8; b++) s += partial[b * NE + tid];
        float mp = s * (1.f / (float)TOKENS);
        v = mp * logf(mp * (float)NE + 1e-9f);
    }
#pragma unroll
    for (int off = 16; off > 0; off >>= 1)
        v += __shfl_down_sync(0xffffffffu, v, off);
    if (tid == 0) out[AUX_OFF] = v;
}

// ---------------- launch ------------------------------------------------------
extern "C" void kernel_launch(void* const* d_in, const int* in_sizes, int n_in,
                              void* d_out, int out_size)
{
    const float* hs   = (const float*)d_in[0];
    const float* mimg = (const float*)d_in[1];
    const float* mgen = (const float*)d_in[2];
    const float* Wg1  = (const float*)d_in[3];
    const float* bg1  = (const float*)d_in[4];
    const float* Wg2  = (const float*)d_in[5];
    const float* bg2  = (const float*)d_in[6];
    const float* Wm1  = (const float*)d_in[7];
    const float* bm1  = (const float*)d_in[8];
    const float* Wm2  = (const float*)d_in[9];
    const float* bm2  = (const float*)d_in[10];
    const float* Ws1  = (const float*)d_in[11];
    const float* bs1  = (const float*)d_in[12];
    const float* Ws2  = (const float*)d_in[13];
    const float* bs2  = (const float*)d_in[14];
    float* out = (float*)d_out;

    float *T1, *T2, *S1, *glog, *slog, *partial;
    float *HSh, *HSl, *ACTh, *ACTl, *Wh, *Wl;
    cudaGetSymbolAddress((void**)&T1,      g_T1);
    cudaGetSymbolAddress((void**)&T2,      g_T2);
    cudaGetSymbolAddress((void**)&S1,      g_S1);
    cudaGetSymbolAddress((void**)&glog,    g_glog);
    cudaGetSymbolAddress((void**)&slog,    g_slog);
    cudaGetSymbolAddress((void**)&partial, g_partial);
    cudaGetSymbolAddress((void**)&HSh,     g_HSh);
    cudaGetSymbolAddress((void**)&HSl,     g_HSl);
    cudaGetSymbolAddress((void**)&ACTh,    g_ACTh);
    cudaGetSymbolAddress((void**)&ACTl,    g_ACTl);
    cudaGetSymbolAddress((void**)&Wh,      g_Wh);
    cudaGetSymbolAddress((void**)&Wl,      g_Wl);

    cudaFuncSetAttribute(gemm_split,
                         cudaFuncAttributeMaxDynamicSharedMemorySize, SMEM_BYTES);

    zero_kernel<<<4096, 256>>>((float4*)out, (int)(2 * C_OFF / 4));

    const int n4_big = TOKENS * HDIM / 4;      // 1M float4
    const int n4_mid = HDIM * H2DIM / 4;       // 512K float4

    dim3 gbig(16, 16);   // N=2048
    dim3 gmid(8, 16);    // N=1024

    // hs split (used by GEMM1 and GEMM3)
    split_kernel<<<2048, 256>>>((const float4*)hs, (float4*)HSh, (float4*)HSl, n4_big);

    // missing-modality encoder: T1 = relu(hs@Wm1+bm1); T2 = T1@Wm2+bm2
    split_kernel<<<2048, 256>>>((const float4*)Wm1, (float4*)Wh, (float4*)Wl, n4_big);
    gemm_split<<<gbig, 256, SMEM_BYTES>>>(HSh, HSl, Wh, Wl, bm1, T1, HDIM, 1);
    split_kernel<<<2048, 256>>>((const float4*)T1, (float4*)ACTh, (float4*)ACTl, n4_big);
    split_kernel<<<2048, 256>>>((const float4*)Wm2, (float4*)Wh, (float4*)Wl, n4_big);
    gemm_split<<<gbig, 256, SMEM_BYTES>>>(ACTh, ACTl, Wh, Wl, bm2, T2, HDIM, 0);

    // generalized router: T1 = relu(hs@Wg1+bg1); glog = T1@Wg2+bg2
    split_kernel<<<2048, 256>>>((const float4*)Wg1, (float4*)Wh, (float4*)Wl, n4_big);
    gemm_split<<<gbig, 256, SMEM_BYTES>>>(HSh, HSl, Wh, Wl, bg1, T1, HDIM, 1);
    logits_kernel<<<512, 128>>>(T1, Wg2, bg2, glog, HDIM);

    // specialized routers
    for (int m = 0; m < NMOD; m++) {
        const float* data = (m == 0) ? mimg : (m == 1) ? mgen : T2;
        if (m < 3)  // m==3 reuses T2 split from m==2
            split_kernel<<<2048, 256>>>((const float4*)data, (float4*)ACTh, (float4*)ACTl, n4_big);
        split_kernel<<<2048, 256>>>((const float4*)(Ws1 + (size_t)m * HDIM * H2DIM),
                                    (float4*)Wh, (float4*)Wl, n4_mid);
        gemm_split<<<gmid, 256, SMEM_BYTES>>>(ACTh, ACTl, Wh, Wl,
                                              bs1 + (size_t)m * H2DIM, S1, H2DIM, 1);
        logits_kernel<<<512, 128>>>(S1, Ws2 + (size_t)m * H2DIM * NE,
                                    bs2 + (size_t)m * NE,
                                    slog + (size_t)m * TOKENS * NE, H2DIM);
    }

    router_kernel<<<8, 256>>>(glog, slog, out, partial);
    aux_kernel<<<1, 32>>>(partial, out);
}